// round 15
// baseline (speedup 1.0000x reference)
#include <cuda_runtime.h>
#include <cuda_fp16.h>
#include <math.h>
#include <stdint.h>

// ---------------------------------------------------------------------------
// SwinTransformerBlock  B=2 D=8 H=56 W=56 C=384  heads=12 hd=32 win=(2,7,7)
// GEMMs: mma.sync.m16n8k16.f16, BK=32, 4-stage cp.async (frozen shape);
//        all 12 ldsm hoisted ahead of the 32 mma per k-iter (sw pipeline).
// LN: warp-per-row.  Attention: 7 warps / 1 m-tile, no max-shift softmax.
// ---------------------------------------------------------------------------

#define NTOK   50176
#define CDIM   384
#define QKVDIM 1152
#define HID    1536
#define NWIN   512
#define NTOKW  98
#define HEADS  12
#define HD     32

// -------------------- scratch (device globals; no allocation) --------------
__device__ __half g_xw_h  [NTOK * CDIM];
__device__ __half g_qkv_h [NTOK * QKVDIM];
__device__ __half g_attn_h[NTOK * CDIM];
__device__ __half g_hid_h [NTOK * HID];
__device__ float  g_xres  [NTOK * CDIM];
__device__ __half g_maskf[256 * 7 * 13 * 128];
__device__ __half g_biasf[HEADS * 7 * 13 * 128];
#define WT_QKV 0
#define WT_PROJ (CDIM * QKVDIM)
#define WT_FC1  (WT_PROJ + CDIM * CDIM)
#define WT_FC2  (WT_FC1 + CDIM * HID)
__device__ __half g_wt_h[CDIM*QKVDIM + CDIM*CDIM + CDIM*HID + HID*CDIM];

// -------------------- helpers ----------------------------------------------
__device__ __forceinline__ uint32_t smem_u32(const void* p) {
    uint32_t a;
    asm("{ .reg .u64 t; cvta.to.shared.u64 t, %1; cvt.u32.u64 %0, t; }" : "=r"(a) : "l"(p));
    return a;
}
__device__ __forceinline__ void cp_async16(uint32_t dst, const void* src) {
    asm volatile("cp.async.ca.shared.global [%0], [%1], 16;" :: "r"(dst), "l"(src));
}
__device__ __forceinline__ void mma16816(float* c, const uint32_t* a, const uint32_t* b) {
    asm volatile("mma.sync.aligned.m16n8k16.row.col.f32.f16.f16.f32 "
        "{%0,%1,%2,%3}, {%4,%5,%6,%7}, {%8,%9}, {%0,%1,%2,%3};"
        : "+f"(c[0]), "+f"(c[1]), "+f"(c[2]), "+f"(c[3])
        : "r"(a[0]), "r"(a[1]), "r"(a[2]), "r"(a[3]), "r"(b[0]), "r"(b[1]));
}
__device__ __forceinline__ void ldsm4(uint32_t* r, uint32_t addr) {
    asm volatile("ldmatrix.sync.aligned.m8n8.x4.shared.b16 {%0,%1,%2,%3}, [%4];"
        : "=r"(r[0]), "=r"(r[1]), "=r"(r[2]), "=r"(r[3]) : "r"(addr));
}
__device__ __forceinline__ void ldsm4t(uint32_t* r, uint32_t addr) {
    asm volatile("ldmatrix.sync.aligned.m8n8.x4.trans.shared.b16 {%0,%1,%2,%3}, [%4];"
        : "=r"(r[0]), "=r"(r[1]), "=r"(r[2]), "=r"(r[3]) : "r"(addr));
}
__device__ __forceinline__ uint32_t h2exp2u(float a0, float a1) {
    __half2 h = __floats2half2_rn(a0, a1);
    uint32_t i = *(uint32_t*)&h, r;
    asm("ex2.approx.f16x2 %0, %1;" : "=r"(r) : "r"(i));
    return r;
}

// -------------------- row permutation (window <-> spatial) -----------------
__device__ __forceinline__ int remap_row(int r) {
    int win = r / NTOKW;
    int n   = r - win * NTOKW;
    int b     = win >> 8;
    int local = win & 255;
    int dblk = local >> 6, hblk = (local >> 3) & 7, wblk = local & 7;
    int wd  = n / 49;
    int rem = n - wd * 49;
    int wh  = rem / 7, ww = rem - wh * 7;
    int d = dblk * 2 + wd + 1; if (d >= 8)  d -= 8;
    int h = hblk * 7 + wh + 3; if (h >= 56) h -= 56;
    int w = wblk * 7 + ww + 3; if (w >= 56) w -= 56;
    return ((b * 8 + d) * 56 + h) * 56 + w;
}

// -------------------- LayerNorm: one warp per row ---------------------------
template<bool GATHER>
__global__ void __launch_bounds__(256) ln_kernel(
    const float* __restrict__ x, const float* __restrict__ gamma,
    const float* __restrict__ beta, __half* __restrict__ out)
{
    const int warp = threadIdx.x >> 5, lane = threadIdx.x & 31;
    const int r = blockIdx.x * 8 + warp;
    const int src = GATHER ? remap_row(r) : r;
    const float* xp = x + (size_t)src * CDIM + lane * 4;

    float4 v0 = *(const float4*)(xp);
    float4 v1 = *(const float4*)(xp + 128);
    float4 v2 = *(const float4*)(xp + 256);

    float s  = v0.x+v0.y+v0.z+v0.w + v1.x+v1.y+v1.z+v1.w + v2.x+v2.y+v2.z+v2.w;
    float sq = v0.x*v0.x+v0.y*v0.y+v0.z*v0.z+v0.w*v0.w
             + v1.x*v1.x+v1.y*v1.y+v1.z*v1.z+v1.w*v1.w
             + v2.x*v2.x+v2.y*v2.y+v2.z*v2.z+v2.w*v2.w;
#pragma unroll
    for (int o = 16; o; o >>= 1) {
        s  += __shfl_xor_sync(0xffffffffu, s,  o);
        sq += __shfl_xor_sync(0xffffffffu, sq, o);
    }
    float mu   = s * (1.0f / CDIM);
    float var  = sq * (1.0f / CDIM) - mu * mu;
    float rstd = rsqrtf(var + 1e-5f);

    const float* gp = gamma + lane * 4;
    const float* bp = beta + lane * 4;
    __half* op = out + (size_t)r * CDIM + lane * 4;
#pragma unroll
    for (int k = 0; k < 3; k++) {
        float4 v = k == 0 ? v0 : (k == 1 ? v1 : v2);
        float4 gg = *(const float4*)(gp + k * 128);
        float4 bb = *(const float4*)(bp + k * 128);
        __half2 h0 = __floats2half2_rn((v.x - mu) * rstd * gg.x + bb.x,
                                       (v.y - mu) * rstd * gg.y + bb.y);
        __half2 h1 = __floats2half2_rn((v.z - mu) * rstd * gg.z + bb.z,
                                       (v.w - mu) * rstd * gg.w + bb.w);
        *(uint2*)(op + k * 128) = make_uint2(*(uint32_t*)&h0, *(uint32_t*)&h1);
    }
}

// -------------------- ALL prep in one launch --------------------------------
#define PREP_T 1728
#define PREP_M 2912
#define PREP_B 137

__device__ __forceinline__ float bias_val(const float* bt, int head, int r, int m) {
    if (r >= NTOKW || m >= NTOKW) return 0.0f;
    int nd = r / 49, nrem = r - nd * 49, nh = nrem / 7, nw = nrem - nh * 7;
    int md = m / 49, mrem = m - md * 49, mh = mrem / 7, mw = mrem - mh * 7;
    int ridx = (nd - md + 1) * 169 + (nh - mh + 6) * 13 + (nw - mw + 6);
    return bt[ridx * HEADS + head];
}

__global__ void __launch_bounds__(256) prep_all(
    const float* __restrict__ w0, const float* __restrict__ w1,
    const float* __restrict__ w2, const float* __restrict__ w3,
    __half* __restrict__ wt,
    const float* __restrict__ mask, __half* __restrict__ mf,
    const float* __restrict__ bias_table, __half* __restrict__ bfr)
{
    int b = blockIdx.x;
    int t = threadIdx.x;
    if (b < PREP_T) {
        __shared__ float tile[32][33];
        const float* W; __half* WT; int K, N, tt;
        if (b < 432)       { W = w0; WT = wt + WT_QKV;  K = CDIM; N = QKVDIM; tt = b; }
        else if (b < 576)  { W = w1; WT = wt + WT_PROJ; K = CDIM; N = CDIM;   tt = b - 432; }
        else if (b < 1152) { W = w2; WT = wt + WT_FC1;  K = CDIM; N = HID;    tt = b - 576; }
        else               { W = w3; WT = wt + WT_FC2;  K = HID;  N = CDIM;   tt = b - 1152; }
        int nx = N / 32;
        int nb = (tt % nx) * 32, kb = (tt / nx) * 32;
        int tx = t & 31, ty = t >> 5;
#pragma unroll
        for (int j = ty; j < 32; j += 8)
            tile[j][tx] = W[(size_t)(kb + j) * N + nb + tx];
        __syncthreads();
#pragma unroll
        for (int j = ty; j < 32; j += 8)
            WT[(size_t)(nb + j) * K + kb + tx] = __float2half(tile[tx][j]);
        return;
    }
    if (b < PREP_T + PREP_M) {
        int e = (b - PREP_T) * 256 + t;
        int lane = e & 31;
        int q = e >> 5;
        int nt = q % 13; q /= 13;
        int mt = q % 7;
        int local = q / 7;
        int g = lane >> 2, j = lane & 3;
        int r0 = mt * 16 + g, r1 = r0 + 8;
        int c0 = nt * 8 + j * 2;
        const float* mp = mask + (size_t)local * NTOKW * NTOKW;
        float vx = (c0     < NTOKW) ? (r0 < NTOKW ? mp[r0 * NTOKW + c0]     : 0.0f) : -1e30f;
        float vy = (c0 + 1 < NTOKW) ? (r0 < NTOKW ? mp[r0 * NTOKW + c0 + 1] : 0.0f) : -1e30f;
        float vz = (c0     < NTOKW) ? (r1 < NTOKW ? mp[r1 * NTOKW + c0]     : 0.0f) : -1e30f;
        float vw = (c0 + 1 < NTOKW) ? (r1 < NTOKW ? mp[r1 * NTOKW + c0 + 1] : 0.0f) : -1e30f;
        __half2 h0 = __floats2half2_rn(vx, vy);
        __half2 h1 = __floats2half2_rn(vz, vw);
        ((uint2*)mf)[e] = make_uint2(*(uint32_t*)&h0, *(uint32_t*)&h1);
        return;
    }
    {
        int e = (b - PREP_T - PREP_M) * 256 + t;
        if (e >= HEADS * 7 * 13 * 32) return;
        int lane = e & 31;
        int q = e >> 5;
        int nt = q % 13; q /= 13;
        int mt = q % 7;
        int head = q / 7;
        int g = lane >> 2, j = lane & 3;
        int r0 = mt * 16 + g, r1 = r0 + 8;
        int c0 = nt * 8 + j * 2;
        __half2 h0 = __floats2half2_rn(bias_val(bias_table, head, r0, c0),
                                       bias_val(bias_table, head, r0, c0 + 1));
        __half2 h1 = __floats2half2_rn(bias_val(bias_table, head, r1, c0),
                                       bias_val(bias_table, head, r1, c0 + 1));
        ((uint2*)bfr)[e] = make_uint2(*(uint32_t*)&h0, *(uint32_t*)&h1);
    }
}

// -------------------- fp16 mma GEMM  BM=BN=128, BK=32 halves, 4 stages -----
#define BKH 32
#define KSTH 40
#define STAGE_B (128 * KSTH * 2)
#define STG 4
#define GSMEM_BYTES (2 * STG * STAGE_B)   // 81920 — frozen

template<int EPI>
__global__ void __launch_bounds__(256, 2) mma_gemm(
    const __half* __restrict__ A, const __half* __restrict__ WT,
    const float* __restrict__ bias, const float* __restrict__ add,
    void* __restrict__ Cv, int M, int N, int K)
{
    extern __shared__ char smem[];
    const uint32_t sAu = smem_u32(smem);
    const uint32_t sBu = sAu + STG * STAGE_B;

    const int tid = threadIdx.x, lane = tid & 31, wid = tid >> 5;
    const int m0 = blockIdx.y * 128, n0 = blockIdx.x * 128;
    const int wm = (wid & 1) * 64, wn = (wid >> 1) * 32;

    const int row = tid >> 1, c16 = (tid & 1) * 16;
    const __half* Agp = A  + (size_t)(m0 + row) * K + c16;
    const __half* Bgp = WT + (size_t)(n0 + row) * K + c16;
    const uint32_t dOff = (uint32_t)(row * KSTH + c16) * 2;
    const int nk = K / BKH;

    const uint32_t aLane = (uint32_t)(wm + (lane & 15)) * 80 + (lane >> 4) * 16;
    const uint32_t bLane = (uint32_t)(wn + ((lane >> 4) * 8) + (lane & 7)) * 80
                         + (((lane >> 3) & 1) * 16);

    float acc[16][4];
#pragma unroll
    for (int i = 0; i < 16; i++)
#pragma unroll
        for (int j = 0; j < 4; j++) acc[i][j] = 0.0f;

#define STAGE_LOAD(slot, ks) do { \
        uint32_t _da = sAu + (uint32_t)(slot) * STAGE_B + dOff; \
        uint32_t _db = sBu + (uint32_t)(slot) * STAGE_B + dOff; \
        const __half* _ga = Agp + (ks) * BKH; \
        const __half* _gb = Bgp + (ks) * BKH; \
        cp_async16(_da, _ga); \
        cp_async16(_da + 16, _ga + 8); \
        cp_async16(_db, _gb); \
        cp_async16(_db + 16, _gb + 8); \
    } while (0)

#pragma unroll
    for (int s = 0; s < STG - 1; s++) {
        if (s < nk) STAGE_LOAD(s, s);
        asm volatile("cp.async.commit_group;");
    }

    for (int ks = 0; ks < nk; ks++) {
        asm volatile("cp.async.wait_group %0;" :: "n"(STG - 2));
        __syncthreads();

        const uint32_t aSt = sAu + (uint32_t)(ks % STG) * STAGE_B + aLane;
        const uint32_t bSt = sBu + (uint32_t)(ks % STG) * STAGE_B + bLane;

        // ---- hoist ALL fragment loads (both kk halves) ----
        uint32_t af[2][4][4], bfr2[2][2][4];
#pragma unroll
        for (int kk = 0; kk < 2; kk++) {
            const uint32_t kOff = kk * 32;
#pragma unroll
            for (int mt = 0; mt < 4; mt++)
                ldsm4(af[kk][mt], aSt + (uint32_t)mt * (16 * 80) + kOff);
            ldsm4(bfr2[kk][0], bSt + kOff);
            ldsm4(bfr2[kk][1], bSt + (16 * 80) + kOff);
        }

        // ---- kk0 mma ----
#pragma unroll
        for (int mt = 0; mt < 4; mt++)
#pragma unroll
            for (int nt = 0; nt < 4; nt++)
                mma16816(acc[mt * 4 + nt], af[0][mt], &bfr2[0][nt >> 1][(nt & 1) * 2]);

        // ---- prefetch next stage between mma halves ----
        int pf = ks + STG - 1;
        if (pf < nk) STAGE_LOAD(pf % STG, pf);
        asm volatile("cp.async.commit_group;");

        // ---- kk1 mma ----
#pragma unroll
        for (int mt = 0; mt < 4; mt++)
#pragma unroll
            for (int nt = 0; nt < 4; nt++)
                mma16816(acc[mt * 4 + nt], af[1][mt], &bfr2[1][nt >> 1][(nt & 1) * 2]);
    }

    const int g = lane >> 2;
    const int j2 = (lane & 3) * 2;
    float* Cf = (float*)Cv;
    __half* Ch = (__half*)Cv;
#pragma unroll
    for (int mt = 0; mt < 4; mt++) {
        int r_lo = m0 + wm + mt * 16 + g;
        int r_hi = r_lo + 8;
        int t_lo = (EPI == 1) ? remap_row(r_lo) : r_lo;
        int t_hi = (EPI == 1) ? remap_row(r_hi) : r_hi;
#pragma unroll
        for (int nt = 0; nt < 4; nt++) {
            int c = n0 + wn + nt * 8 + j2;
            float2 bv = *(const float2*)(bias + c);
            const float* a = acc[mt * 4 + nt];
            float x0 = a[0] + bv.x, x1 = a[1] + bv.y;
            float x2 = a[2] + bv.x, x3 = a[3] + bv.y;
            if (EPI == 2) {
                x0 = 0.5f * x0 * (1.0f + erff(x0 * 0.70710678118654752f));
                x1 = 0.5f * x1 * (1.0f + erff(x1 * 0.70710678118654752f));
                x2 = 0.5f * x2 * (1.0f + erff(x2 * 0.70710678118654752f));
                x3 = 0.5f * x3 * (1.0f + erff(x3 * 0.70710678118654752f));
            }
            if (EPI == 1 || EPI == 3) {
                float2 alo = *(const float2*)(add + (size_t)t_lo * N + c);
                float2 ahi = *(const float2*)(add + (size_t)t_hi * N + c);
                x0 += alo.x; x1 += alo.y; x2 += ahi.x; x3 += ahi.y;
                *(float2*)(Cf + (size_t)t_lo * N + c) = make_float2(x0, x1);
                *(float2*)(Cf + (size_t)t_hi * N + c) = make_float2(x2, x3);
            } else {
                *(__half2*)(Ch + (size_t)t_lo * N + c) = __floats2half2_rn(x0, x1);
                *(__half2*)(Ch + (size_t)t_hi * N + c) = __floats2half2_rn(x2, x3);
            }
        }
    }
}

// -------------------- fp16 attention: 7 warps, one m-tile per warp ----------
#define AST 40
#define AROWS 112
#define ATHREADS 224

__global__ void __launch_bounds__(ATHREADS) attn_h(
    const __half* __restrict__ qkv, const __half* __restrict__ maskf,
    const __half* __restrict__ biasf, __half* __restrict__ out)
{
    __shared__ __half S[3 * AROWS * AST];
    __half* Qs = S;
    __half* Ks = S + AROWS * AST;
    __half* Vs = S + 2 * AROWS * AST;

    const int win = blockIdx.y, head = blockIdx.x, tid = threadIdx.x;

    for (int i = tid; i < 3 * AROWS * AST / 2; i += ATHREADS)
        ((uint32_t*)S)[i] = 0;
    __syncthreads();

    const __half* base = qkv + (size_t)win * NTOKW * QKVDIM + head * HD;
#pragma unroll
    for (int it = 0; it < 7; it++) {
        int i = it * ATHREADS + tid;
        int m = i >> 4, d2 = i & 15;
        const __half2* p = (const __half2*)(base + (size_t)m * QKVDIM) + d2;
        ((__half2*)(Qs + m * AST))[d2] = p[0];
        ((__half2*)(Ks + m * AST))[d2] = p[CDIM / 2];
        ((__half2*)(Vs + m * AST))[d2] = p[CDIM];
    }
    __syncthreads();

    const int mt = tid >> 5, lane = tid & 31;
    const int mb = mt * 16;
    const uint32_t sQ = smem_u32(Qs), sK = smem_u32(Ks), sV = smem_u32(Vs);
    const uint32_t aAddr = sQ + (uint32_t)(lane & 15) * 80 + (lane >> 4) * 16;
    const uint32_t bKAddr = sK + (uint32_t)(((lane >> 4) * 8) + (lane & 7)) * 80
                          + (((lane >> 3) & 1) * 16);
    const uint32_t bVAddr = sV + (uint32_t)((((lane >> 3) & 1) * 8) + (lane & 7)) * 80
                          + ((lane >> 4) * 16);
    const int g = lane >> 2, j2 = (lane & 3) * 2;
    const float SC = 0.17677669529663687f;
    const float L2E = 1.4426950408889634f;

    float c[13][4];
#pragma unroll
    for (int nt = 0; nt < 13; nt++)
        c[nt][0] = c[nt][1] = c[nt][2] = c[nt][3] = 0.0f;
#pragma unroll
    for (int kk = 0; kk < 2; kk++) {
        uint32_t aQ[4];
        ldsm4(aQ, aAddr + (uint32_t)mb * 80 + kk * 32);
#pragma unroll
        for (int grp = 0; grp < 7; grp++) {
            uint32_t bK[4];
            ldsm4(bK, bKAddr + (uint32_t)grp * 1280 + kk * 32);
            mma16816(c[grp * 2], aQ, bK);
            if (grp < 6) mma16816(c[grp * 2 + 1], aQ, bK + 2);
        }
    }
    const uint2* mf2 = (const uint2*)maskf +
        (((size_t)(win & 255) * 7 + mt) * 13) * 32 + lane;
    const uint2* bf2 = (const uint2*)biasf +
        (((size_t)head * 7 + mt) * 13) * 32 + lane;
    uint32_t p[13][2];
    float s0 = 0.0f, s1 = 0.0f;
#pragma unroll
    for (int nt = 0; nt < 13; nt++) {
        uint2 mu = mf2[nt * 32];
        uint2 bu = bf2[nt * 32];
        float2 m0 = __half22float2(*(__half2*)&mu.x);
        float2 m1 = __half22float2(*(__half2*)&mu.y);
        float2 b0 = __half22float2(*(__half2*)&bu.x);
        float2 b1 = __half22float2(*(__half2*)&bu.y);
        float l0 = fmaf(c[nt][0], SC, m0.x + b0.x);
        float l1 = fmaf(c[nt][1], SC, m0.y + b0.y);
        float l2 = fmaf(c[nt][2], SC, m1.x + b1.x);
        float l3 = fmaf(c[nt][3], SC, m1.y + b1.y);
        uint32_t e0 = h2exp2u(l0 * L2E, l1 * L2E);
        uint32_t e1 = h2exp2u(l2 * L2E, l3 * L2E);
        p[nt][0] = e0; p[nt][1] = e1;
        float2 f0 = __half22float2(*(__half2*)&e0);
        float2 f1 = __half22float2(*(__half2*)&e1);
        s0 += f0.x + f0.y; s1 += f1.x + f1.y;
    }
    s0 += __shfl_xor_sync(0xffffffffu, s0, 1);
    s0 += __shfl_xor_sync(0xffffffffu, s0, 2);
    s1 += __shfl_xor_sync(0xffffffffu, s1, 1);
    s1 += __shfl_xor_sync(0xffffffffu, s1, 2);
    float inv0 = 1.0f / s0, inv1 = 1.0f / s1;

    float o[4][4];
#pragma unroll
    for (int a = 0; a < 4; a++)
#pragma unroll
        for (int b = 0; b < 4; b++) o[a][b] = 0.0f;
#pragma unroll
    for (int kc = 0; kc < 7; kc++) {
        uint32_t ap[4];
        ap[0] = p[2 * kc][0];
        ap[1] = p[2 * kc][1];
        ap[2] = (kc < 6) ? p[2 * kc + 1][0] : 0u;
        ap[3] = (kc < 6) ? p[2 * kc + 1][1] : 0u;
        uint32_t bv0[4], bv1[4];
        ldsm4t(bv0, bVAddr + (uint32_t)kc * 1280);
        ldsm4t(bv1, bVAddr + (uint32_t)kc * 1280 + 32);
        mma16816(o[0], ap, bv0);
        mma16816(o[1], ap, bv0 + 2);
        mma16816(o[2], ap, bv1);
        mma16816(o[3], ap, bv1 + 2);
    }
    const int r0 = mb + g, r1 = r0 + 8;
    if (r0 < NTOKW) {
        __half* op = out + ((size_t)win * NTOKW + r0) * CDIM + head * HD;
#pragma unroll
        for (int nd = 0; nd < 4; nd++)
            *(__half2*)(op + nd * 8 + j2) =
                __floats2half2_rn(o[nd][0] * inv0, o[nd][1] * inv0);
    }
    if (r1 < NTOKW) {
        __half* op = out + ((size_t)win * NTOKW + r1) * CDIM + head * HD;
#pragma unroll
        for (int nd = 0; nd < 4; nd++)
            *(__half2*)(op + nd * 8 + j2) =
                __floats2half2_rn(o[nd][2] * inv1, o[nd][3] * inv1);
    }
}

// ---------------------------------------------------------------------------
extern "C" void kernel_launch(void* const* d_in, const int* in_sizes, int n_in,
                              void* d_out, int out_size)
{
    (void)in_sizes; (void)n_in; (void)out_size;
    const float* x          = (const float*)d_in[0];
    const float* mask       = (const float*)d_in[1];
    const float* norm1_g    = (const float*)d_in[2];
    const float* norm1_b    = (const float*)d_in[3];
    const float* qkv_w      = (const float*)d_in[4];
    const float* qkv_b      = (const float*)d_in[5];
    const float* bias_table = (const float*)d_in[6];
    const float* proj_w     = (const float*)d_in[7];
    const float* proj_b     = (const float*)d_in[8];
    const float* norm2_g    = (const float*)d_in[9];
    const float* norm2_b    = (const float*)d_in[10];
    const float* fc1_w      = (const float*)d_in[11];
    const float* fc1_b      = (const float*)d_in[12];
    const float* fc2_w      = (const float*)d_in[13];
    const float* fc2_b      = (const float*)d_in[14];
    float* out = (float*)d_out;

    __half *p_xw, *p_qkv, *p_attn, *p_hid, *p_wt, *p_maskf, *p_biasf;
    float *p_xres;
    cudaGetSymbolAddress((void**)&p_xw,    g_xw_h);
    cudaGetSymbolAddress((void**)&p_qkv,   g_qkv_h);
    cudaGetSymbolAddress((void**)&p_attn,  g_attn_h);
    cudaGetSymbolAddress((void**)&p_hid,   g_hid_h);
    cudaGetSymbolAddress((void**)&p_xres,  g_xres);
    cudaGetSymbolAddress((void**)&p_wt,    g_wt_h);
    cudaGetSymbolAddress((void**)&p_maskf, g_maskf);
    cudaGetSymbolAddress((void**)&p_biasf, g_biasf);

    cudaFuncSetAttribute(mma_gemm<0>, cudaFuncAttributeMaxDynamicSharedMemorySize, GSMEM_BYTES);
    cudaFuncSetAttribute(mma_gemm<1>, cudaFuncAttributeMaxDynamicSharedMemorySize, GSMEM_BYTES);
    cudaFuncSetAttribute(mma_gemm<2>, cudaFuncAttributeMaxDynamicSharedMemorySize, GSMEM_BYTES);
    cudaFuncSetAttribute(mma_gemm<3>, cudaFuncAttributeMaxDynamicSharedMemorySize, GSMEM_BYTES);

    // prep — ONE launch
    prep_all<<<PREP_T + PREP_M + PREP_B, 256>>>(
        qkv_w, proj_w, fc1_w, fc2_w, p_wt, mask, p_maskf, bias_table, p_biasf);

    // 1. LN1 + roll + window partition (gather) -> fp16
    ln_kernel<true><<<NTOK / 8, 256>>>(x, norm1_g, norm1_b, p_xw);

    // 2. qkv
    mma_gemm<0><<<dim3(QKVDIM/128, NTOK/128), 256, GSMEM_BYTES>>>(
        p_xw, p_wt + WT_QKV, qkv_b, nullptr, p_qkv, NTOK, QKVDIM, CDIM);

    // 3. windowed attention
    attn_h<<<dim3(HEADS, NWIN), ATHREADS>>>(p_qkv, p_maskf, p_biasf, p_attn);

    // 4. proj + scatter + shortcut -> fp32 xres
    mma_gemm<1><<<dim3(CDIM/128, NTOK/128), 256, GSMEM_BYTES>>>(
        p_attn, p_wt + WT_PROJ, proj_b, x, p_xres, NTOK, CDIM, CDIM);

    // 5. LN2 -> fp16
    ln_kernel<false><<<NTOK / 8, 256>>>(p_xres, norm2_g, norm2_b, p_xw);

    // 6. fc1 + GELU -> fp16
    mma_gemm<2><<<dim3(HID/128, NTOK/128), 256, GSMEM_BYTES>>>(
        p_xw, p_wt + WT_FC1, fc1_b, nullptr, p_hid, NTOK, HID, CDIM);

    // 7. fc2 + residual -> fp32 out
    mma_gemm<3><<<dim3(CDIM/128, NTOK/128), 256, GSMEM_BYTES>>>(
        p_hid, p_wt + WT_FC2, fc2_b, p_xres, out, NTOK, CDIM, HID);
}

// round 16
// speedup vs baseline: 1.0138x; 1.0138x over previous
#include <cuda_runtime.h>
#include <cuda_fp16.h>
#include <math.h>
#include <stdint.h>

// ---------------------------------------------------------------------------
// SwinTransformerBlock  B=2 D=8 H=56 W=56 C=384  heads=12 hd=32 win=(2,7,7)
// GEMMs: mma.sync.m16n8k16.f16, BK=32, 4-stage cp.async (frozen shape + order).
// LN: warp-per-row.  Attention: 7 warps / 1 m-tile, no max-shift softmax.
// Prep merged into one launch.  (Exact restore of the 870.5us configuration.)
// ---------------------------------------------------------------------------

#define NTOK   50176
#define CDIM   384
#define QKVDIM 1152
#define HID    1536
#define NWIN   512
#define NTOKW  98
#define HEADS  12
#define HD     32

// -------------------- scratch (device globals; no allocation) --------------
__device__ __half g_xw_h  [NTOK * CDIM];
__device__ __half g_qkv_h [NTOK * QKVDIM];
__device__ __half g_attn_h[NTOK * CDIM];
__device__ __half g_hid_h [NTOK * HID];
__device__ float  g_xres  [NTOK * CDIM];
__device__ __half g_maskf[256 * 7 * 13 * 128];
__device__ __half g_biasf[HEADS * 7 * 13 * 128];
#define WT_QKV 0
#define WT_PROJ (CDIM * QKVDIM)
#define WT_FC1  (WT_PROJ + CDIM * CDIM)
#define WT_FC2  (WT_FC1 + CDIM * HID)
__device__ __half g_wt_h[CDIM*QKVDIM + CDIM*CDIM + CDIM*HID + HID*CDIM];

// -------------------- helpers ----------------------------------------------
__device__ __forceinline__ uint32_t smem_u32(const void* p) {
    uint32_t a;
    asm("{ .reg .u64 t; cvta.to.shared.u64 t, %1; cvt.u32.u64 %0, t; }" : "=r"(a) : "l"(p));
    return a;
}
__device__ __forceinline__ void cp_async16(uint32_t dst, const void* src) {
    asm volatile("cp.async.ca.shared.global [%0], [%1], 16;" :: "r"(dst), "l"(src));
}
__device__ __forceinline__ void mma16816(float* c, const uint32_t* a, const uint32_t* b) {
    asm volatile("mma.sync.aligned.m16n8k16.row.col.f32.f16.f16.f32 "
        "{%0,%1,%2,%3}, {%4,%5,%6,%7}, {%8,%9}, {%0,%1,%2,%3};"
        : "+f"(c[0]), "+f"(c[1]), "+f"(c[2]), "+f"(c[3])
        : "r"(a[0]), "r"(a[1]), "r"(a[2]), "r"(a[3]), "r"(b[0]), "r"(b[1]));
}
__device__ __forceinline__ void ldsm4(uint32_t* r, uint32_t addr) {
    asm volatile("ldmatrix.sync.aligned.m8n8.x4.shared.b16 {%0,%1,%2,%3}, [%4];"
        : "=r"(r[0]), "=r"(r[1]), "=r"(r[2]), "=r"(r[3]) : "r"(addr));
}
__device__ __forceinline__ void ldsm4t(uint32_t* r, uint32_t addr) {
    asm volatile("ldmatrix.sync.aligned.m8n8.x4.trans.shared.b16 {%0,%1,%2,%3}, [%4];"
        : "=r"(r[0]), "=r"(r[1]), "=r"(r[2]), "=r"(r[3]) : "r"(addr));
}
__device__ __forceinline__ uint32_t h2exp2u(float a0, float a1) {
    __half2 h = __floats2half2_rn(a0, a1);
    uint32_t i = *(uint32_t*)&h, r;
    asm("ex2.approx.f16x2 %0, %1;" : "=r"(r) : "r"(i));
    return r;
}

// -------------------- row permutation (window <-> spatial) -----------------
__device__ __forceinline__ int remap_row(int r) {
    int win = r / NTOKW;
    int n   = r - win * NTOKW;
    int b     = win >> 8;
    int local = win & 255;
    int dblk = local >> 6, hblk = (local >> 3) & 7, wblk = local & 7;
    int wd  = n / 49;
    int rem = n - wd * 49;
    int wh  = rem / 7, ww = rem - wh * 7;
    int d = dblk * 2 + wd + 1; if (d >= 8)  d -= 8;
    int h = hblk * 7 + wh + 3; if (h >= 56) h -= 56;
    int w = wblk * 7 + ww + 3; if (w >= 56) w -= 56;
    return ((b * 8 + d) * 56 + h) * 56 + w;
}

// -------------------- LayerNorm: one warp per row ---------------------------
template<bool GATHER>
__global__ void __launch_bounds__(256) ln_kernel(
    const float* __restrict__ x, const float* __restrict__ gamma,
    const float* __restrict__ beta, __half* __restrict__ out)
{
    const int warp = threadIdx.x >> 5, lane = threadIdx.x & 31;
    const int r = blockIdx.x * 8 + warp;
    const int src = GATHER ? remap_row(r) : r;
    const float* xp = x + (size_t)src * CDIM + lane * 4;

    float4 v0 = *(const float4*)(xp);
    float4 v1 = *(const float4*)(xp + 128);
    float4 v2 = *(const float4*)(xp + 256);

    float s  = v0.x+v0.y+v0.z+v0.w + v1.x+v1.y+v1.z+v1.w + v2.x+v2.y+v2.z+v2.w;
    float sq = v0.x*v0.x+v0.y*v0.y+v0.z*v0.z+v0.w*v0.w
             + v1.x*v1.x+v1.y*v1.y+v1.z*v1.z+v1.w*v1.w
             + v2.x*v2.x+v2.y*v2.y+v2.z*v2.z+v2.w*v2.w;
#pragma unroll
    for (int o = 16; o; o >>= 1) {
        s  += __shfl_xor_sync(0xffffffffu, s,  o);
        sq += __shfl_xor_sync(0xffffffffu, sq, o);
    }
    float mu   = s * (1.0f / CDIM);
    float var  = sq * (1.0f / CDIM) - mu * mu;
    float rstd = rsqrtf(var + 1e-5f);

    const float* gp = gamma + lane * 4;
    const float* bp = beta + lane * 4;
    __half* op = out + (size_t)r * CDIM + lane * 4;
#pragma unroll
    for (int k = 0; k < 3; k++) {
        float4 v = k == 0 ? v0 : (k == 1 ? v1 : v2);
        float4 gg = *(const float4*)(gp + k * 128);
        float4 bb = *(const float4*)(bp + k * 128);
        __half2 h0 = __floats2half2_rn((v.x - mu) * rstd * gg.x + bb.x,
                                       (v.y - mu) * rstd * gg.y + bb.y);
        __half2 h1 = __floats2half2_rn((v.z - mu) * rstd * gg.z + bb.z,
                                       (v.w - mu) * rstd * gg.w + bb.w);
        *(uint2*)(op + k * 128) = make_uint2(*(uint32_t*)&h0, *(uint32_t*)&h1);
    }
}

// -------------------- ALL prep in one launch --------------------------------
#define PREP_T 1728
#define PREP_M 2912
#define PREP_B 137

__device__ __forceinline__ float bias_val(const float* bt, int head, int r, int m) {
    if (r >= NTOKW || m >= NTOKW) return 0.0f;
    int nd = r / 49, nrem = r - nd * 49, nh = nrem / 7, nw = nrem - nh * 7;
    int md = m / 49, mrem = m - md * 49, mh = mrem / 7, mw = mrem - mh * 7;
    int ridx = (nd - md + 1) * 169 + (nh - mh + 6) * 13 + (nw - mw + 6);
    return bt[ridx * HEADS + head];
}

__global__ void __launch_bounds__(256) prep_all(
    const float* __restrict__ w0, const float* __restrict__ w1,
    const float* __restrict__ w2, const float* __restrict__ w3,
    __half* __restrict__ wt,
    const float* __restrict__ mask, __half* __restrict__ mf,
    const float* __restrict__ bias_table, __half* __restrict__ bfr)
{
    int b = blockIdx.x;
    int t = threadIdx.x;
    if (b < PREP_T) {
        __shared__ float tile[32][33];
        const float* W; __half* WT; int K, N, tt;
        if (b < 432)       { W = w0; WT = wt + WT_QKV;  K = CDIM; N = QKVDIM; tt = b; }
        else if (b < 576)  { W = w1; WT = wt + WT_PROJ; K = CDIM; N = CDIM;   tt = b - 432; }
        else if (b < 1152) { W = w2; WT = wt + WT_FC1;  K = CDIM; N = HID;    tt = b - 576; }
        else               { W = w3; WT = wt + WT_FC2;  K = HID;  N = CDIM;   tt = b - 1152; }
        int nx = N / 32;
        int nb = (tt % nx) * 32, kb = (tt / nx) * 32;
        int tx = t & 31, ty = t >> 5;
#pragma unroll
        for (int j = ty; j < 32; j += 8)
            tile[j][tx] = W[(size_t)(kb + j) * N + nb + tx];
        __syncthreads();
#pragma unroll
        for (int j = ty; j < 32; j += 8)
            WT[(size_t)(nb + j) * K + kb + tx] = __float2half(tile[tx][j]);
        return;
    }
    if (b < PREP_T + PREP_M) {
        int e = (b - PREP_T) * 256 + t;
        int lane = e & 31;
        int q = e >> 5;
        int nt = q % 13; q /= 13;
        int mt = q % 7;
        int local = q / 7;
        int g = lane >> 2, j = lane & 3;
        int r0 = mt * 16 + g, r1 = r0 + 8;
        int c0 = nt * 8 + j * 2;
        const float* mp = mask + (size_t)local * NTOKW * NTOKW;
        float vx = (c0     < NTOKW) ? (r0 < NTOKW ? mp[r0 * NTOKW + c0]     : 0.0f) : -1e30f;
        float vy = (c0 + 1 < NTOKW) ? (r0 < NTOKW ? mp[r0 * NTOKW + c0 + 1] : 0.0f) : -1e30f;
        float vz = (c0     < NTOKW) ? (r1 < NTOKW ? mp[r1 * NTOKW + c0]     : 0.0f) : -1e30f;
        float vw = (c0 + 1 < NTOKW) ? (r1 < NTOKW ? mp[r1 * NTOKW + c0 + 1] : 0.0f) : -1e30f;
        __half2 h0 = __floats2half2_rn(vx, vy);
        __half2 h1 = __floats2half2_rn(vz, vw);
        ((uint2*)mf)[e] = make_uint2(*(uint32_t*)&h0, *(uint32_t*)&h1);
        return;
    }
    {
        int e = (b - PREP_T - PREP_M) * 256 + t;
        if (e >= HEADS * 7 * 13 * 32) return;
        int lane = e & 31;
        int q = e >> 5;
        int nt = q % 13; q /= 13;
        int mt = q % 7;
        int head = q / 7;
        int g = lane >> 2, j = lane & 3;
        int r0 = mt * 16 + g, r1 = r0 + 8;
        int c0 = nt * 8 + j * 2;
        __half2 h0 = __floats2half2_rn(bias_val(bias_table, head, r0, c0),
                                       bias_val(bias_table, head, r0, c0 + 1));
        __half2 h1 = __floats2half2_rn(bias_val(bias_table, head, r1, c0),
                                       bias_val(bias_table, head, r1, c0 + 1));
        ((uint2*)bfr)[e] = make_uint2(*(uint32_t*)&h0, *(uint32_t*)&h1);
    }
}

// -------------------- fp16 mma GEMM  BM=BN=128, BK=32 halves, 4 stages -----
#define BKH 32
#define KSTH 40
#define STAGE_B (128 * KSTH * 2)
#define STG 4
#define GSMEM_BYTES (2 * STG * STAGE_B)   // 81920 — frozen

template<int EPI>
__global__ void __launch_bounds__(256, 2) mma_gemm(
    const __half* __restrict__ A, const __half* __restrict__ WT,
    const float* __restrict__ bias, const float* __restrict__ add,
    void* __restrict__ Cv, int M, int N, int K)
{
    extern __shared__ char smem[];
    const uint32_t sAu = smem_u32(smem);
    const uint32_t sBu = sAu + STG * STAGE_B;

    const int tid = threadIdx.x, lane = tid & 31, wid = tid >> 5;
    const int m0 = blockIdx.y * 128, n0 = blockIdx.x * 128;
    const int wm = (wid & 1) * 64, wn = (wid >> 1) * 32;

    const int row = tid >> 1, c16 = (tid & 1) * 16;
    const __half* Agp = A  + (size_t)(m0 + row) * K + c16;
    const __half* Bgp = WT + (size_t)(n0 + row) * K + c16;
    const uint32_t dOff = (uint32_t)(row * KSTH + c16) * 2;
    const int nk = K / BKH;

    const uint32_t aLane = (uint32_t)(wm + (lane & 15)) * 80 + (lane >> 4) * 16;
    const uint32_t bLane = (uint32_t)(wn + ((lane >> 4) * 8) + (lane & 7)) * 80
                         + (((lane >> 3) & 1) * 16);

    float acc[16][4];
#pragma unroll
    for (int i = 0; i < 16; i++)
#pragma unroll
        for (int j = 0; j < 4; j++) acc[i][j] = 0.0f;

#define STAGE_LOAD(slot, ks) do { \
        uint32_t _da = sAu + (uint32_t)(slot) * STAGE_B + dOff; \
        uint32_t _db = sBu + (uint32_t)(slot) * STAGE_B + dOff; \
        const __half* _ga = Agp + (ks) * BKH; \
        const __half* _gb = Bgp + (ks) * BKH; \
        cp_async16(_da, _ga); \
        cp_async16(_da + 16, _ga + 8); \
        cp_async16(_db, _gb); \
        cp_async16(_db + 16, _gb + 8); \
    } while (0)

#define COMPUTE_KK(kk) do { \
        uint32_t af[4][4], bfr2[2][4]; \
        const uint32_t kOff = (kk) * 32; \
        _Pragma("unroll") \
        for (int mt = 0; mt < 4; mt++) \
            ldsm4(af[mt], aSt + (uint32_t)mt * (16 * 80) + kOff); \
        ldsm4(bfr2[0], bSt + kOff); \
        ldsm4(bfr2[1], bSt + (16 * 80) + kOff); \
        _Pragma("unroll") \
        for (int mt = 0; mt < 4; mt++) { \
            _Pragma("unroll") \
            for (int nt = 0; nt < 4; nt++) \
                mma16816(acc[mt * 4 + nt], af[mt], &bfr2[nt >> 1][(nt & 1) * 2]); \
        } \
    } while (0)

#pragma unroll
    for (int s = 0; s < STG - 1; s++) {
        if (s < nk) STAGE_LOAD(s, s);
        asm volatile("cp.async.commit_group;");
    }

    for (int ks = 0; ks < nk; ks++) {
        asm volatile("cp.async.wait_group %0;" :: "n"(STG - 2));
        __syncthreads();

        const uint32_t aSt = sAu + (uint32_t)(ks % STG) * STAGE_B + aLane;
        const uint32_t bSt = sBu + (uint32_t)(ks % STG) * STAGE_B + bLane;

        COMPUTE_KK(0);

        int pf = ks + STG - 1;
        if (pf < nk) STAGE_LOAD(pf % STG, pf);
        asm volatile("cp.async.commit_group;");

        COMPUTE_KK(1);
    }

    const int g = lane >> 2;
    const int j2 = (lane & 3) * 2;
    float* Cf = (float*)Cv;
    __half* Ch = (__half*)Cv;
#pragma unroll
    for (int mt = 0; mt < 4; mt++) {
        int r_lo = m0 + wm + mt * 16 + g;
        int r_hi = r_lo + 8;
        int t_lo = (EPI == 1) ? remap_row(r_lo) : r_lo;
        int t_hi = (EPI == 1) ? remap_row(r_hi) : r_hi;
#pragma unroll
        for (int nt = 0; nt < 4; nt++) {
            int c = n0 + wn + nt * 8 + j2;
            float2 bv = *(const float2*)(bias + c);
            const float* a = acc[mt * 4 + nt];
            float x0 = a[0] + bv.x, x1 = a[1] + bv.y;
            float x2 = a[2] + bv.x, x3 = a[3] + bv.y;
            if (EPI == 2) {
                x0 = 0.5f * x0 * (1.0f + erff(x0 * 0.70710678118654752f));
                x1 = 0.5f * x1 * (1.0f + erff(x1 * 0.70710678118654752f));
                x2 = 0.5f * x2 * (1.0f + erff(x2 * 0.70710678118654752f));
                x3 = 0.5f * x3 * (1.0f + erff(x3 * 0.70710678118654752f));
            }
            if (EPI == 1 || EPI == 3) {
                float2 alo = *(const float2*)(add + (size_t)t_lo * N + c);
                float2 ahi = *(const float2*)(add + (size_t)t_hi * N + c);
                x0 += alo.x; x1 += alo.y; x2 += ahi.x; x3 += ahi.y;
                *(float2*)(Cf + (size_t)t_lo * N + c) = make_float2(x0, x1);
                *(float2*)(Cf + (size_t)t_hi * N + c) = make_float2(x2, x3);
            } else {
                *(__half2*)(Ch + (size_t)t_lo * N + c) = __floats2half2_rn(x0, x1);
                *(__half2*)(Ch + (size_t)t_hi * N + c) = __floats2half2_rn(x2, x3);
            }
        }
    }
}

// -------------------- fp16 attention: 7 warps, one m-tile per warp ----------
#define AST 40
#define AROWS 112
#define ATHREADS 224

__global__ void __launch_bounds__(ATHREADS) attn_h(
    const __half* __restrict__ qkv, const __half* __restrict__ maskf,
    const __half* __restrict__ biasf, __half* __restrict__ out)
{
    __shared__ __half S[3 * AROWS * AST];
    __half* Qs = S;
    __half* Ks = S + AROWS * AST;
    __half* Vs = S + 2 * AROWS * AST;

    const int win = blockIdx.y, head = blockIdx.x, tid = threadIdx.x;

    for (int i = tid; i < 3 * AROWS * AST / 2; i += ATHREADS)
        ((uint32_t*)S)[i] = 0;
    __syncthreads();

    const __half* base = qkv + (size_t)win * NTOKW * QKVDIM + head * HD;
#pragma unroll
    for (int it = 0; it < 7; it++) {
        int i = it * ATHREADS + tid;
        int m = i >> 4, d2 = i & 15;
        const __half2* p = (const __half2*)(base + (size_t)m * QKVDIM) + d2;
        ((__half2*)(Qs + m * AST))[d2] = p[0];
        ((__half2*)(Ks + m * AST))[d2] = p[CDIM / 2];
        ((__half2*)(Vs + m * AST))[d2] = p[CDIM];
    }
    __syncthreads();

    const int mt = tid >> 5, lane = tid & 31;
    const int mb = mt * 16;
    const uint32_t sQ = smem_u32(Qs), sK = smem_u32(Ks), sV = smem_u32(Vs);
    const uint32_t aAddr = sQ + (uint32_t)(lane & 15) * 80 + (lane >> 4) * 16;
    const uint32_t bKAddr = sK + (uint32_t)(((lane >> 4) * 8) + (lane & 7)) * 80
                          + (((lane >> 3) & 1) * 16);
    const uint32_t bVAddr = sV + (uint32_t)((((lane >> 3) & 1) * 8) + (lane & 7)) * 80
                          + ((lane >> 4) * 16);
    const int g = lane >> 2, j2 = (lane & 3) * 2;
    const float SC = 0.17677669529663687f;
    const float L2E = 1.4426950408889634f;

    float c[13][4];
#pragma unroll
    for (int nt = 0; nt < 13; nt++)
        c[nt][0] = c[nt][1] = c[nt][2] = c[nt][3] = 0.0f;
#pragma unroll
    for (int kk = 0; kk < 2; kk++) {
        uint32_t aQ[4];
        ldsm4(aQ, aAddr + (uint32_t)mb * 80 + kk * 32);
#pragma unroll
        for (int grp = 0; grp < 7; grp++) {
            uint32_t bK[4];
            ldsm4(bK, bKAddr + (uint32_t)grp * 1280 + kk * 32);
            mma16816(c[grp * 2], aQ, bK);
            if (grp < 6) mma16816(c[grp * 2 + 1], aQ, bK + 2);
        }
    }
    const uint2* mf2 = (const uint2*)maskf +
        (((size_t)(win & 255) * 7 + mt) * 13) * 32 + lane;
    const uint2* bf2 = (const uint2*)biasf +
        (((size_t)head * 7 + mt) * 13) * 32 + lane;
    uint32_t p[13][2];
    float s0 = 0.0f, s1 = 0.0f;
#pragma unroll
    for (int nt = 0; nt < 13; nt++) {
        uint2 mu = mf2[nt * 32];
        uint2 bu = bf2[nt * 32];
        float2 m0 = __half22float2(*(__half2*)&mu.x);
        float2 m1 = __half22float2(*(__half2*)&mu.y);
        float2 b0 = __half22float2(*(__half2*)&bu.x);
        float2 b1 = __half22float2(*(__half2*)&bu.y);
        float l0 = fmaf(c[nt][0], SC, m0.x + b0.x);
        float l1 = fmaf(c[nt][1], SC, m0.y + b0.y);
        float l2 = fmaf(c[nt][2], SC, m1.x + b1.x);
        float l3 = fmaf(c[nt][3], SC, m1.y + b1.y);
        uint32_t e0 = h2exp2u(l0 * L2E, l1 * L2E);
        uint32_t e1 = h2exp2u(l2 * L2E, l3 * L2E);
        p[nt][0] = e0; p[nt][1] = e1;
        float2 f0 = __half22float2(*(__half2*)&e0);
        float2 f1 = __half22float2(*(__half2*)&e1);
        s0 += f0.x + f0.y; s1 += f1.x + f1.y;
    }
    s0 += __shfl_xor_sync(0xffffffffu, s0, 1);
    s0 += __shfl_xor_sync(0xffffffffu, s0, 2);
    s1 += __shfl_xor_sync(0xffffffffu, s1, 1);
    s1 += __shfl_xor_sync(0xffffffffu, s1, 2);
    float inv0 = 1.0f / s0, inv1 = 1.0f / s1;

    float o[4][4];
#pragma unroll
    for (int a = 0; a < 4; a++)
#pragma unroll
        for (int b = 0; b < 4; b++) o[a][b] = 0.0f;
#pragma unroll
    for (int kc = 0; kc < 7; kc++) {
        uint32_t ap[4];
        ap[0] = p[2 * kc][0];
        ap[1] = p[2 * kc][1];
        ap[2] = (kc < 6) ? p[2 * kc + 1][0] : 0u;
        ap[3] = (kc < 6) ? p[2 * kc + 1][1] : 0u;
        uint32_t bv0[4], bv1[4];
        ldsm4t(bv0, bVAddr + (uint32_t)kc * 1280);
        ldsm4t(bv1, bVAddr + (uint32_t)kc * 1280 + 32);
        mma16816(o[0], ap, bv0);
        mma16816(o[1], ap, bv0 + 2);
        mma16816(o[2], ap, bv1);
        mma16816(o[3], ap, bv1 + 2);
    }
    const int r0 = mb + g, r1 = r0 + 8;
    if (r0 < NTOKW) {
        __half* op = out + ((size_t)win * NTOKW + r0) * CDIM + head * HD;
#pragma unroll
        for (int nd = 0; nd < 4; nd++)
            *(__half2*)(op + nd * 8 + j2) =
                __floats2half2_rn(o[nd][0] * inv0, o[nd][1] * inv0);
    }
    if (r1 < NTOKW) {
        __half* op = out + ((size_t)win * NTOKW + r1) * CDIM + head * HD;
#pragma unroll
        for (int nd = 0; nd < 4; nd++)
            *(__half2*)(op + nd * 8 + j2) =
                __floats2half2_rn(o[nd][2] * inv1, o[nd][3] * inv1);
    }
}

// ---------------------------------------------------------------------------
extern "C" void kernel_launch(void* const* d_in, const int* in_sizes, int n_in,
                              void* d_out, int out_size)
{
    (void)in_sizes; (void)n_in; (void)out_size;
    const float* x          = (const float*)d_in[0];
    const float* mask       = (const float*)d_in[1];
    const float* norm1_g    = (const float*)d_in[2];
    const float* norm1_b    = (const float*)d_in[3];
    const float* qkv_w      = (const float*)d_in[4];
    const float* qkv_b      = (const float*)d_in[5];
    const float* bias_table = (const float*)d_in[6];
    const float* proj_w     = (const float*)d_in[7];
    const float* proj_b     = (const float*)d_in[8];
    const float* norm2_g    = (const float*)d_in[9];
    const float* norm2_b    = (const float*)d_in[10];
    const float* fc1_w      = (const float*)d_in[11];
    const float* fc1_b      = (const float*)d_in[12];
    const float* fc2_w      = (const float*)d_in[13];
    const float* fc2_b      = (const float*)d_in[14];
    float* out = (float*)d_out;

    __half *p_xw, *p_qkv, *p_attn, *p_hid, *p_wt, *p_maskf, *p_biasf;
    float *p_xres;
    cudaGetSymbolAddress((void**)&p_xw,    g_xw_h);
    cudaGetSymbolAddress((void**)&p_qkv,   g_qkv_h);
    cudaGetSymbolAddress((void**)&p_attn,  g_attn_h);
    cudaGetSymbolAddress((void**)&p_hid,   g_hid_h);
    cudaGetSymbolAddress((void**)&p_xres,  g_xres);
    cudaGetSymbolAddress((void**)&p_wt,    g_wt_h);
    cudaGetSymbolAddress((void**)&p_maskf, g_maskf);
    cudaGetSymbolAddress((void**)&p_biasf, g_biasf);

    cudaFuncSetAttribute(mma_gemm<0>, cudaFuncAttributeMaxDynamicSharedMemorySize, GSMEM_BYTES);
    cudaFuncSetAttribute(mma_gemm<1>, cudaFuncAttributeMaxDynamicSharedMemorySize, GSMEM_BYTES);
    cudaFuncSetAttribute(mma_gemm<2>, cudaFuncAttributeMaxDynamicSharedMemorySize, GSMEM_BYTES);
    cudaFuncSetAttribute(mma_gemm<3>, cudaFuncAttributeMaxDynamicSharedMemorySize, GSMEM_BYTES);

    // prep — ONE launch
    prep_all<<<PREP_T + PREP_M + PREP_B, 256>>>(
        qkv_w, proj_w, fc1_w, fc2_w, p_wt, mask, p_maskf, bias_table, p_biasf);

    // 1. LN1 + roll + window partition (gather) -> fp16
    ln_kernel<true><<<NTOK / 8, 256>>>(x, norm1_g, norm1_b, p_xw);

    // 2. qkv
    mma_gemm<0><<<dim3(QKVDIM/128, NTOK/128), 256, GSMEM_BYTES>>>(
        p_xw, p_wt + WT_QKV, qkv_b, nullptr, p_qkv, NTOK, QKVDIM, CDIM);

    // 3. windowed attention
    attn_h<<<dim3(HEADS, NWIN), ATHREADS>>>(p_qkv, p_maskf, p_biasf, p_attn);

    // 4. proj + scatter + shortcut -> fp32 xres
    mma_gemm<1><<<dim3(CDIM/128, NTOK/128), 256, GSMEM_BYTES>>>(
        p_attn, p_wt + WT_PROJ, proj_b, x, p_xres, NTOK, CDIM, CDIM);

    // 5. LN2 -> fp16
    ln_kernel<false><<<NTOK / 8, 256>>>(p_xres, norm2_g, norm2_b, p_xw);

    // 6. fc1 + GELU -> fp16
    mma_gemm<2><<<dim3(HID/128, NTOK/128), 256, GSMEM_BYTES>>>(
        p_xw, p_wt + WT_FC1, fc1_b, nullptr, p_hid, NTOK, HID, CDIM);

    // 7. fc2 + residual -> fp32 out
    mma_gemm<3><<<dim3(CDIM/128, NTOK/128), 256, GSMEM_BYTES>>>(
        p_hid, p_wt + WT_FC2, fc2_b, p_xres, out, NTOK, CDIM, HID);
}

// round 17
// speedup vs baseline: 1.0171x; 1.0032x over previous
#include <cuda_runtime.h>
#include <cuda_fp16.h>
#include <math.h>
#include <stdint.h>

// ---------------------------------------------------------------------------
// SwinTransformerBlock  B=2 D=8 H=56 W=56 C=384  heads=12 hd=32 win=(2,7,7)
// GEMMs: mma.sync.m16n8k16.f16, BK=32, 4-stage cp.async (frozen shape+order).
// LN: warp-per-row (fp32 or fp16 input).  Attention: 7 warps / 1 m-tile.
// Residual xres stored fp16.  Prep merged into one launch.
// ---------------------------------------------------------------------------

#define NTOK   50176
#define CDIM   384
#define QKVDIM 1152
#define HID    1536
#define NWIN   512
#define NTOKW  98
#define HEADS  12
#define HD     32

// -------------------- scratch (device globals; no allocation) --------------
__device__ __half g_xw_h  [NTOK * CDIM];
__device__ __half g_qkv_h [NTOK * QKVDIM];
__device__ __half g_attn_h[NTOK * CDIM];
__device__ __half g_hid_h [NTOK * HID];
__device__ __half g_xres_h[NTOK * CDIM];      // fp16 residual
__device__ __half g_maskf[256 * 7 * 13 * 128];
__device__ __half g_biasf[HEADS * 7 * 13 * 128];
#define WT_QKV 0
#define WT_PROJ (CDIM * QKVDIM)
#define WT_FC1  (WT_PROJ + CDIM * CDIM)
#define WT_FC2  (WT_FC1 + CDIM * HID)
__device__ __half g_wt_h[CDIM*QKVDIM + CDIM*CDIM + CDIM*HID + HID*CDIM];

// -------------------- helpers ----------------------------------------------
__device__ __forceinline__ uint32_t smem_u32(const void* p) {
    uint32_t a;
    asm("{ .reg .u64 t; cvta.to.shared.u64 t, %1; cvt.u32.u64 %0, t; }" : "=r"(a) : "l"(p));
    return a;
}
__device__ __forceinline__ void cp_async16(uint32_t dst, const void* src) {
    asm volatile("cp.async.ca.shared.global [%0], [%1], 16;" :: "r"(dst), "l"(src));
}
__device__ __forceinline__ void mma16816(float* c, const uint32_t* a, const uint32_t* b) {
    asm volatile("mma.sync.aligned.m16n8k16.row.col.f32.f16.f16.f32 "
        "{%0,%1,%2,%3}, {%4,%5,%6,%7}, {%8,%9}, {%0,%1,%2,%3};"
        : "+f"(c[0]), "+f"(c[1]), "+f"(c[2]), "+f"(c[3])
        : "r"(a[0]), "r"(a[1]), "r"(a[2]), "r"(a[3]), "r"(b[0]), "r"(b[1]));
}
__device__ __forceinline__ void ldsm4(uint32_t* r, uint32_t addr) {
    asm volatile("ldmatrix.sync.aligned.m8n8.x4.shared.b16 {%0,%1,%2,%3}, [%4];"
        : "=r"(r[0]), "=r"(r[1]), "=r"(r[2]), "=r"(r[3]) : "r"(addr));
}
__device__ __forceinline__ void ldsm4t(uint32_t* r, uint32_t addr) {
    asm volatile("ldmatrix.sync.aligned.m8n8.x4.trans.shared.b16 {%0,%1,%2,%3}, [%4];"
        : "=r"(r[0]), "=r"(r[1]), "=r"(r[2]), "=r"(r[3]) : "r"(addr));
}
__device__ __forceinline__ uint32_t h2exp2u(float a0, float a1) {
    __half2 h = __floats2half2_rn(a0, a1);
    uint32_t i = *(uint32_t*)&h, r;
    asm("ex2.approx.f16x2 %0, %1;" : "=r"(r) : "r"(i));
    return r;
}

// -------------------- row permutation (window <-> spatial) -----------------
__device__ __forceinline__ int remap_row(int r) {
    int win = r / NTOKW;
    int n   = r - win * NTOKW;
    int b     = win >> 8;
    int local = win & 255;
    int dblk = local >> 6, hblk = (local >> 3) & 7, wblk = local & 7;
    int wd  = n / 49;
    int rem = n - wd * 49;
    int wh  = rem / 7, ww = rem - wh * 7;
    int d = dblk * 2 + wd + 1; if (d >= 8)  d -= 8;
    int h = hblk * 7 + wh + 3; if (h >= 56) h -= 56;
    int w = wblk * 7 + ww + 3; if (w >= 56) w -= 56;
    return ((b * 8 + d) * 56 + h) * 56 + w;
}

// -------------------- LayerNorm: one warp per row, templated input ---------
template<bool GATHER, bool HIN>
__global__ void __launch_bounds__(256) ln_kernel(
    const void* __restrict__ xv, const float* __restrict__ gamma,
    const float* __restrict__ beta, __half* __restrict__ out)
{
    const int warp = threadIdx.x >> 5, lane = threadIdx.x & 31;
    const int r = blockIdx.x * 8 + warp;
    const int src = GATHER ? remap_row(r) : r;

    float4 v0, v1, v2;
    if (HIN) {
        const __half* xp = (const __half*)xv + (size_t)src * CDIM + lane * 4;
#pragma unroll
        for (int k = 0; k < 3; k++) {
            uint2 u = *(const uint2*)(xp + k * 128);
            float2 a = __half22float2(*(__half2*)&u.x);
            float2 b = __half22float2(*(__half2*)&u.y);
            float4 v = make_float4(a.x, a.y, b.x, b.y);
            if (k == 0) v0 = v; else if (k == 1) v1 = v; else v2 = v;
        }
    } else {
        const float* xp = (const float*)xv + (size_t)src * CDIM + lane * 4;
        v0 = *(const float4*)(xp);
        v1 = *(const float4*)(xp + 128);
        v2 = *(const float4*)(xp + 256);
    }

    float s  = v0.x+v0.y+v0.z+v0.w + v1.x+v1.y+v1.z+v1.w + v2.x+v2.y+v2.z+v2.w;
    float sq = v0.x*v0.x+v0.y*v0.y+v0.z*v0.z+v0.w*v0.w
             + v1.x*v1.x+v1.y*v1.y+v1.z*v1.z+v1.w*v1.w
             + v2.x*v2.x+v2.y*v2.y+v2.z*v2.z+v2.w*v2.w;
#pragma unroll
    for (int o = 16; o; o >>= 1) {
        s  += __shfl_xor_sync(0xffffffffu, s,  o);
        sq += __shfl_xor_sync(0xffffffffu, sq, o);
    }
    float mu   = s * (1.0f / CDIM);
    float var  = sq * (1.0f / CDIM) - mu * mu;
    float rstd = rsqrtf(var + 1e-5f);

    const float* gp = gamma + lane * 4;
    const float* bp = beta + lane * 4;
    __half* op = out + (size_t)r * CDIM + lane * 4;
#pragma unroll
    for (int k = 0; k < 3; k++) {
        float4 v = k == 0 ? v0 : (k == 1 ? v1 : v2);
        float4 gg = *(const float4*)(gp + k * 128);
        float4 bb = *(const float4*)(bp + k * 128);
        __half2 h0 = __floats2half2_rn((v.x - mu) * rstd * gg.x + bb.x,
                                       (v.y - mu) * rstd * gg.y + bb.y);
        __half2 h1 = __floats2half2_rn((v.z - mu) * rstd * gg.z + bb.z,
                                       (v.w - mu) * rstd * gg.w + bb.w);
        *(uint2*)(op + k * 128) = make_uint2(*(uint32_t*)&h0, *(uint32_t*)&h1);
    }
}

// -------------------- ALL prep in one launch --------------------------------
#define PREP_T 1728
#define PREP_M 2912
#define PREP_B 137

__device__ __forceinline__ float bias_val(const float* bt, int head, int r, int m) {
    if (r >= NTOKW || m >= NTOKW) return 0.0f;
    int nd = r / 49, nrem = r - nd * 49, nh = nrem / 7, nw = nrem - nh * 7;
    int md = m / 49, mrem = m - md * 49, mh = mrem / 7, mw = mrem - mh * 7;
    int ridx = (nd - md + 1) * 169 + (nh - mh + 6) * 13 + (nw - mw + 6);
    return bt[ridx * HEADS + head];
}

__global__ void __launch_bounds__(256) prep_all(
    const float* __restrict__ w0, const float* __restrict__ w1,
    const float* __restrict__ w2, const float* __restrict__ w3,
    __half* __restrict__ wt,
    const float* __restrict__ mask, __half* __restrict__ mf,
    const float* __restrict__ bias_table, __half* __restrict__ bfr)
{
    int b = blockIdx.x;
    int t = threadIdx.x;
    if (b < PREP_T) {
        __shared__ float tile[32][33];
        const float* W; __half* WT; int K, N, tt;
        if (b < 432)       { W = w0; WT = wt + WT_QKV;  K = CDIM; N = QKVDIM; tt = b; }
        else if (b < 576)  { W = w1; WT = wt + WT_PROJ; K = CDIM; N = CDIM;   tt = b - 432; }
        else if (b < 1152) { W = w2; WT = wt + WT_FC1;  K = CDIM; N = HID;    tt = b - 576; }
        else               { W = w3; WT = wt + WT_FC2;  K = HID;  N = CDIM;   tt = b - 1152; }
        int nx = N / 32;
        int nb = (tt % nx) * 32, kb = (tt / nx) * 32;
        int tx = t & 31, ty = t >> 5;
#pragma unroll
        for (int j = ty; j < 32; j += 8)
            tile[j][tx] = W[(size_t)(kb + j) * N + nb + tx];
        __syncthreads();
#pragma unroll
        for (int j = ty; j < 32; j += 8)
            WT[(size_t)(nb + j) * K + kb + tx] = __float2half(tile[tx][j]);
        return;
    }
    if (b < PREP_T + PREP_M) {
        int e = (b - PREP_T) * 256 + t;
        int lane = e & 31;
        int q = e >> 5;
        int nt = q % 13; q /= 13;
        int mt = q % 7;
        int local = q / 7;
        int g = lane >> 2, j = lane & 3;
        int r0 = mt * 16 + g, r1 = r0 + 8;
        int c0 = nt * 8 + j * 2;
        const float* mp = mask + (size_t)local * NTOKW * NTOKW;
        float vx = (c0     < NTOKW) ? (r0 < NTOKW ? mp[r0 * NTOKW + c0]     : 0.0f) : -1e30f;
        float vy = (c0 + 1 < NTOKW) ? (r0 < NTOKW ? mp[r0 * NTOKW + c0 + 1] : 0.0f) : -1e30f;
        float vz = (c0     < NTOKW) ? (r1 < NTOKW ? mp[r1 * NTOKW + c0]     : 0.0f) : -1e30f;
        float vw = (c0 + 1 < NTOKW) ? (r1 < NTOKW ? mp[r1 * NTOKW + c0 + 1] : 0.0f) : -1e30f;
        __half2 h0 = __floats2half2_rn(vx, vy);
        __half2 h1 = __floats2half2_rn(vz, vw);
        ((uint2*)mf)[e] = make_uint2(*(uint32_t*)&h0, *(uint32_t*)&h1);
        return;
    }
    {
        int e = (b - PREP_T - PREP_M) * 256 + t;
        if (e >= HEADS * 7 * 13 * 32) return;
        int lane = e & 31;
        int q = e >> 5;
        int nt = q % 13; q /= 13;
        int mt = q % 7;
        int head = q / 7;
        int g = lane >> 2, j = lane & 3;
        int r0 = mt * 16 + g, r1 = r0 + 8;
        int c0 = nt * 8 + j * 2;
        __half2 h0 = __floats2half2_rn(bias_val(bias_table, head, r0, c0),
                                       bias_val(bias_table, head, r0, c0 + 1));
        __half2 h1 = __floats2half2_rn(bias_val(bias_table, head, r1, c0),
                                       bias_val(bias_table, head, r1, c0 + 1));
        ((uint2*)bfr)[e] = make_uint2(*(uint32_t*)&h0, *(uint32_t*)&h1);
    }
}

// -------------------- fp16 mma GEMM  BM=BN=128, BK=32 halves, 4 stages -----
// EPI 0: qkv -> half        EPI 1: proj + x(f32) -> xres (half, scattered)
// EPI 2: gelu -> half       EPI 3: fc2 + xres(half) -> out (float)
#define BKH 32
#define KSTH 40
#define STAGE_B (128 * KSTH * 2)
#define STG 4
#define GSMEM_BYTES (2 * STG * STAGE_B)   // 81920 — frozen

template<int EPI>
__global__ void __launch_bounds__(256, 2) mma_gemm(
    const __half* __restrict__ A, const __half* __restrict__ WT,
    const float* __restrict__ bias, const void* __restrict__ addv,
    void* __restrict__ Cv, int M, int N, int K)
{
    extern __shared__ char smem[];
    const uint32_t sAu = smem_u32(smem);
    const uint32_t sBu = sAu + STG * STAGE_B;

    const int tid = threadIdx.x, lane = tid & 31, wid = tid >> 5;
    const int m0 = blockIdx.y * 128, n0 = blockIdx.x * 128;
    const int wm = (wid & 1) * 64, wn = (wid >> 1) * 32;

    const int row = tid >> 1, c16 = (tid & 1) * 16;
    const __half* Agp = A  + (size_t)(m0 + row) * K + c16;
    const __half* Bgp = WT + (size_t)(n0 + row) * K + c16;
    const uint32_t dOff = (uint32_t)(row * KSTH + c16) * 2;
    const int nk = K / BKH;

    const uint32_t aLane = (uint32_t)(wm + (lane & 15)) * 80 + (lane >> 4) * 16;
    const uint32_t bLane = (uint32_t)(wn + ((lane >> 4) * 8) + (lane & 7)) * 80
                         + (((lane >> 3) & 1) * 16);

    float acc[16][4];
#pragma unroll
    for (int i = 0; i < 16; i++)
#pragma unroll
        for (int j = 0; j < 4; j++) acc[i][j] = 0.0f;

#define STAGE_LOAD(slot, ks) do { \
        uint32_t _da = sAu + (uint32_t)(slot) * STAGE_B + dOff; \
        uint32_t _db = sBu + (uint32_t)(slot) * STAGE_B + dOff; \
        const __half* _ga = Agp + (ks) * BKH; \
        const __half* _gb = Bgp + (ks) * BKH; \
        cp_async16(_da, _ga); \
        cp_async16(_da + 16, _ga + 8); \
        cp_async16(_db, _gb); \
        cp_async16(_db + 16, _gb + 8); \
    } while (0)

#define COMPUTE_KK(kk) do { \
        uint32_t af[4][4], bfr2[2][4]; \
        const uint32_t kOff = (kk) * 32; \
        _Pragma("unroll") \
        for (int mt = 0; mt < 4; mt++) \
            ldsm4(af[mt], aSt + (uint32_t)mt * (16 * 80) + kOff); \
        ldsm4(bfr2[0], bSt + kOff); \
        ldsm4(bfr2[1], bSt + (16 * 80) + kOff); \
        _Pragma("unroll") \
        for (int mt = 0; mt < 4; mt++) { \
            _Pragma("unroll") \
            for (int nt = 0; nt < 4; nt++) \
                mma16816(acc[mt * 4 + nt], af[mt], &bfr2[nt >> 1][(nt & 1) * 2]); \
        } \
    } while (0)

#pragma unroll
    for (int s = 0; s < STG - 1; s++) {
        if (s < nk) STAGE_LOAD(s, s);
        asm volatile("cp.async.commit_group;");
    }

    for (int ks = 0; ks < nk; ks++) {
        asm volatile("cp.async.wait_group %0;" :: "n"(STG - 2));
        __syncthreads();

        const uint32_t aSt = sAu + (uint32_t)(ks % STG) * STAGE_B + aLane;
        const uint32_t bSt = sBu + (uint32_t)(ks % STG) * STAGE_B + bLane;

        COMPUTE_KK(0);

        int pf = ks + STG - 1;
        if (pf < nk) STAGE_LOAD(pf % STG, pf);
        asm volatile("cp.async.commit_group;");

        COMPUTE_KK(1);
    }

    const int g = lane >> 2;
    const int j2 = (lane & 3) * 2;
    float* Cf = (float*)Cv;
    __half* Ch = (__half*)Cv;
    const float* addf = (const float*)addv;
    const __half* addh = (const __half*)addv;
#pragma unroll
    for (int mt = 0; mt < 4; mt++) {
        int r_lo = m0 + wm + mt * 16 + g;
        int r_hi = r_lo + 8;
        int t_lo = (EPI == 1) ? remap_row(r_lo) : r_lo;
        int t_hi = (EPI == 1) ? remap_row(r_hi) : r_hi;
#pragma unroll
        for (int nt = 0; nt < 4; nt++) {
            int c = n0 + wn + nt * 8 + j2;
            float2 bv = *(const float2*)(bias + c);
            const float* a = acc[mt * 4 + nt];
            float x0 = a[0] + bv.x, x1 = a[1] + bv.y;
            float x2 = a[2] + bv.x, x3 = a[3] + bv.y;
            if (EPI == 2) {
                x0 = 0.5f * x0 * (1.0f + erff(x0 * 0.70710678118654752f));
                x1 = 0.5f * x1 * (1.0f + erff(x1 * 0.70710678118654752f));
                x2 = 0.5f * x2 * (1.0f + erff(x2 * 0.70710678118654752f));
                x3 = 0.5f * x3 * (1.0f + erff(x3 * 0.70710678118654752f));
            }
            if (EPI == 1) {
                // read fp32 shortcut x, write fp16 xres (scattered)
                float2 alo = *(const float2*)(addf + (size_t)t_lo * N + c);
                float2 ahi = *(const float2*)(addf + (size_t)t_hi * N + c);
                x0 += alo.x; x1 += alo.y; x2 += ahi.x; x3 += ahi.y;
                *(__half2*)(Ch + (size_t)t_lo * N + c) = __floats2half2_rn(x0, x1);
                *(__half2*)(Ch + (size_t)t_hi * N + c) = __floats2half2_rn(x2, x3);
            } else if (EPI == 3) {
                // read fp16 xres, write fp32 final out
                uint32_t ul = *(const uint32_t*)(addh + (size_t)t_lo * N + c);
                uint32_t uh = *(const uint32_t*)(addh + (size_t)t_hi * N + c);
                float2 alo = __half22float2(*(__half2*)&ul);
                float2 ahi = __half22float2(*(__half2*)&uh);
                x0 += alo.x; x1 += alo.y; x2 += ahi.x; x3 += ahi.y;
                *(float2*)(Cf + (size_t)t_lo * N + c) = make_float2(x0, x1);
                *(float2*)(Cf + (size_t)t_hi * N + c) = make_float2(x2, x3);
            } else {
                *(__half2*)(Ch + (size_t)t_lo * N + c) = __floats2half2_rn(x0, x1);
                *(__half2*)(Ch + (size_t)t_hi * N + c) = __floats2half2_rn(x2, x3);
            }
        }
    }
}

// -------------------- fp16 attention: 7 warps, one m-tile per warp ----------
#define AST 40
#define AROWS 112
#define ATHREADS 224

__global__ void __launch_bounds__(ATHREADS) attn_h(
    const __half* __restrict__ qkv, const __half* __restrict__ maskf,
    const __half* __restrict__ biasf, __half* __restrict__ out)
{
    __shared__ __half S[3 * AROWS * AST];
    __half* Qs = S;
    __half* Ks = S + AROWS * AST;
    __half* Vs = S + 2 * AROWS * AST;

    const int win = blockIdx.y, head = blockIdx.x, tid = threadIdx.x;

    // zero only pad rows [98,112) of each array (must be finite for mma/exp)
    for (int i = tid; i < 3 * 14 * (AST / 2); i += ATHREADS) {
        int arr = i / (14 * 20);
        int rem = i - arr * (14 * 20);
        int r = 98 + rem / 20;
        int c2 = rem % 20;
        ((uint32_t*)(S + arr * AROWS * AST + r * AST))[c2] = 0;
    }

    const __half* base = qkv + (size_t)win * NTOKW * QKVDIM + head * HD;
#pragma unroll
    for (int it = 0; it < 7; it++) {            // 1568 / 224 = 7 exact
        int i = it * ATHREADS + tid;
        int m = i >> 4, d2 = i & 15;
        const __half2* p = (const __half2*)(base + (size_t)m * QKVDIM) + d2;
        ((__half2*)(Qs + m * AST))[d2] = p[0];
        ((__half2*)(Ks + m * AST))[d2] = p[CDIM / 2];
        ((__half2*)(Vs + m * AST))[d2] = p[CDIM];
    }
    __syncthreads();

    const int mt = tid >> 5, lane = tid & 31;
    const int mb = mt * 16;
    const uint32_t sQ = smem_u32(Qs), sK = smem_u32(Ks), sV = smem_u32(Vs);
    const uint32_t aAddr = sQ + (uint32_t)(lane & 15) * 80 + (lane >> 4) * 16;
    const uint32_t bKAddr = sK + (uint32_t)(((lane >> 4) * 8) + (lane & 7)) * 80
                          + (((lane >> 3) & 1) * 16);
    const uint32_t bVAddr = sV + (uint32_t)((((lane >> 3) & 1) * 8) + (lane & 7)) * 80
                          + ((lane >> 4) * 16);
    const int g = lane >> 2, j2 = (lane & 3) * 2;
    const float SC = 0.17677669529663687f;
    const float L2E = 1.4426950408889634f;

    float c[13][4];
#pragma unroll
    for (int nt = 0; nt < 13; nt++)
        c[nt][0] = c[nt][1] = c[nt][2] = c[nt][3] = 0.0f;
#pragma unroll
    for (int kk = 0; kk < 2; kk++) {
        uint32_t aQ[4];
        ldsm4(aQ, aAddr + (uint32_t)mb * 80 + kk * 32);
#pragma unroll
        for (int grp = 0; grp < 7; grp++) {
            uint32_t bK[4];
            ldsm4(bK, bKAddr + (uint32_t)grp * 1280 + kk * 32);
            mma16816(c[grp * 2], aQ, bK);
            if (grp < 6) mma16816(c[grp * 2 + 1], aQ, bK + 2);
        }
    }
    const uint2* mf2 = (const uint2*)maskf +
        (((size_t)(win & 255) * 7 + mt) * 13) * 32 + lane;
    const uint2* bf2 = (const uint2*)biasf +
        (((size_t)head * 7 + mt) * 13) * 32 + lane;
    uint32_t p[13][2];
    float s0 = 0.0f, s1 = 0.0f;
#pragma unroll
    for (int nt = 0; nt < 13; nt++) {
        uint2 mu = mf2[nt * 32];
        uint2 bu = bf2[nt * 32];
        float2 m0 = __half22float2(*(__half2*)&mu.x);
        float2 m1 = __half22float2(*(__half2*)&mu.y);
        float2 b0 = __half22float2(*(__half2*)&bu.x);
        float2 b1 = __half22float2(*(__half2*)&bu.y);
        float l0 = fmaf(c[nt][0], SC, m0.x + b0.x);
        float l1 = fmaf(c[nt][1], SC, m0.y + b0.y);
        float l2 = fmaf(c[nt][2], SC, m1.x + b1.x);
        float l3 = fmaf(c[nt][3], SC, m1.y + b1.y);
        uint32_t e0 = h2exp2u(l0 * L2E, l1 * L2E);
        uint32_t e1 = h2exp2u(l2 * L2E, l3 * L2E);
        p[nt][0] = e0; p[nt][1] = e1;
        float2 f0 = __half22float2(*(__half2*)&e0);
        float2 f1 = __half22float2(*(__half2*)&e1);
        s0 += f0.x + f0.y; s1 += f1.x + f1.y;
    }
    s0 += __shfl_xor_sync(0xffffffffu, s0, 1);
    s0 += __shfl_xor_sync(0xffffffffu, s0, 2);
    s1 += __shfl_xor_sync(0xffffffffu, s1, 1);
    s1 += __shfl_xor_sync(0xffffffffu, s1, 2);
    float inv0 = 1.0f / s0, inv1 = 1.0f / s1;

    float o[4][4];
#pragma unroll
    for (int a = 0; a < 4; a++)
#pragma unroll
        for (int b = 0; b < 4; b++) o[a][b] = 0.0f;
#pragma unroll
    for (int kc = 0; kc < 7; kc++) {
        uint32_t ap[4];
        ap[0] = p[2 * kc][0];
        ap[1] = p[2 * kc][1];
        ap[2] = (kc < 6) ? p[2 * kc + 1][0] : 0u;
        ap[3] = (kc < 6) ? p[2 * kc + 1][1] : 0u;
        uint32_t bv0[4], bv1[4];
        ldsm4t(bv0, bVAddr + (uint32_t)kc * 1280);
        ldsm4t(bv1, bVAddr + (uint32_t)kc * 1280 + 32);
        mma16816(o[0], ap, bv0);
        mma16816(o[1], ap, bv0 + 2);
        mma16816(o[2], ap, bv1);
        mma16816(o[3], ap, bv1 + 2);
    }
    const int r0 = mb + g, r1 = r0 + 8;
    if (r0 < NTOKW) {
        __half* op = out + ((size_t)win * NTOKW + r0) * CDIM + head * HD;
#pragma unroll
        for (int nd = 0; nd < 4; nd++)
            *(__half2*)(op + nd * 8 + j2) =
                __floats2half2_rn(o[nd][0] * inv0, o[nd][1] * inv0);
    }
    if (r1 < NTOKW) {
        __half* op = out + ((size_t)win * NTOKW + r1) * CDIM + head * HD;
#pragma unroll
        for (int nd = 0; nd < 4; nd++)
            *(__half2*)(op + nd * 8 + j2) =
                __floats2half2_rn(o[nd][2] * inv1, o[nd][3] * inv1);
    }
}

// ---------------------------------------------------------------------------
extern "C" void kernel_launch(void* const* d_in, const int* in_sizes, int n_in,
                              void* d_out, int out_size)
{
    (void)in_sizes; (void)n_in; (void)out_size;
    const float* x          = (const float*)d_in[0];
    const float* mask       = (const float*)d_in[1];
    const float* norm1_g    = (const float*)d_in[2];
    const float* norm1_b    = (const float*)d_in[3];
    const float* qkv_w      = (const float*)d_in[4];
    const float* qkv_b      = (const float*)d_in[5];
    const float* bias_table = (const float*)d_in[6];
    const float* proj_w     = (const float*)d_in[7];
    const float* proj_b     = (const float*)d_in[8];
    const float* norm2_g    = (const float*)d_in[9];
    const float* norm2_b    = (const float*)d_in[10];
    const float* fc1_w      = (const float*)d_in[11];
    const float* fc1_b      = (const float*)d_in[12];
    const float* fc2_w      = (const float*)d_in[13];
    const float* fc2_b      = (const float*)d_in[14];
    float* out = (float*)d_out;

    __half *p_xw, *p_qkv, *p_attn, *p_hid, *p_xres, *p_wt, *p_maskf, *p_biasf;
    cudaGetSymbolAddress((void**)&p_xw,    g_xw_h);
    cudaGetSymbolAddress((void**)&p_qkv,   g_qkv_h);
    cudaGetSymbolAddress((void**)&p_attn,  g_attn_h);
    cudaGetSymbolAddress((void**)&p_hid,   g_hid_h);
    cudaGetSymbolAddress((void**)&p_xres,  g_xres_h);
    cudaGetSymbolAddress((void**)&p_wt,    g_wt_h);
    cudaGetSymbolAddress((void**)&p_maskf, g_maskf);
    cudaGetSymbolAddress((void**)&p_biasf, g_biasf);

    cudaFuncSetAttribute(mma_gemm<0>, cudaFuncAttributeMaxDynamicSharedMemorySize, GSMEM_BYTES);
    cudaFuncSetAttribute(mma_gemm<1>, cudaFuncAttributeMaxDynamicSharedMemorySize, GSMEM_BYTES);
    cudaFuncSetAttribute(mma_gemm<2>, cudaFuncAttributeMaxDynamicSharedMemorySize, GSMEM_BYTES);
    cudaFuncSetAttribute(mma_gemm<3>, cudaFuncAttributeMaxDynamicSharedMemorySize, GSMEM_BYTES);

    // prep — ONE launch
    prep_all<<<PREP_T + PREP_M + PREP_B, 256>>>(
        qkv_w, proj_w, fc1_w, fc2_w, p_wt, mask, p_maskf, bias_table, p_biasf);

    // 1. LN1 + roll + window partition (gather) -> fp16
    ln_kernel<true, false><<<NTOK / 8, 256>>>(x, norm1_g, norm1_b, p_xw);

    // 2. qkv
    mma_gemm<0><<<dim3(QKVDIM/128, NTOK/128), 256, GSMEM_BYTES>>>(
        p_xw, p_wt + WT_QKV, qkv_b, nullptr, p_qkv, NTOK, QKVDIM, CDIM);

    // 3. windowed attention
    attn_h<<<dim3(HEADS, NWIN), ATHREADS>>>(p_qkv, p_maskf, p_biasf, p_attn);

    // 4. proj + scatter + shortcut(f32 x) -> fp16 xres
    mma_gemm<1><<<dim3(CDIM/128, NTOK/128), 256, GSMEM_BYTES>>>(
        p_attn, p_wt + WT_PROJ, proj_b, x, p_xres, NTOK, CDIM, CDIM);

    // 5. LN2 (fp16 input) -> fp16
    ln_kernel<false, true><<<NTOK / 8, 256>>>(p_xres, norm2_g, norm2_b, p_xw);

    // 6. fc1 + GELU -> fp16
    mma_gemm<2><<<dim3(HID/128, NTOK/128), 256, GSMEM_BYTES>>>(
        p_xw, p_wt + WT_FC1, fc1_b, nullptr, p_hid, NTOK, HID, CDIM);

    // 7. fc2 + residual(fp16 xres) -> fp32 out
    mma_gemm<3><<<dim3(CDIM/128, NTOK/128), 256, GSMEM_BYTES>>>(
        p_hid, p_wt + WT_FC2, fc2_b, p_xres, out, NTOK, CDIM, HID);
}